// round 11
// baseline (speedup 1.0000x reference)
#include <cuda_runtime.h>

#define Bn 32
#define Nn 4096
#define Kn 16
#define PTS 128                 // points per block (2 per thread, 128 threads)
#define NBLK (Nn / PTS)         // 32 blocks per batch
#define GRIDA (Bn * NBLK)       // 1024 blocks x 128 threads

// Deterministic scratch (no allocations allowed)
__device__ float g_comb[GRIDA];             // rec + kld partial (pre-weighted)
__device__ float g_col_partial[GRIDA * Kn]; // assign column partials
__device__ unsigned int g_count = 0;

__device__ __forceinline__ float flog2(float x) {
    float y; asm("lg2.approx.f32 %0, %1;" : "=f"(y) : "f"(x)); return y;
}
__device__ __forceinline__ float fexp2(float x) {
    float y; asm("ex2.approx.f32 %0, %1;" : "=f"(y) : "f"(x)); return y;
}

__global__ __launch_bounds__(128, 8) void loss_fused_kernel(
    const float* __restrict__ pc, const float* __restrict__ normals,
    const float* __restrict__ randn, const float* __restrict__ scale,
    const float* __restrict__ shapes, const float* __restrict__ rotate,
    const float* __restrict__ pam, const float* __restrict__ assign,
    const float* __restrict__ exist, const float* __restrict__ mu,
    const float* __restrict__ logvar, const float* __restrict__ trans,
    float* __restrict__ out)
{
    // sP stride 20 (16B aligned): [0-8]=R, [9-11]=scale, [12-13]=he, [14-16]=cc=R^T mean
    __shared__ __align__(16) float sP[Kn * 20];
    __shared__ float sM[Kn * 3];          // raw means (staging only)
    __shared__ float sA[PTS * 17];        // assign rows, stride-17
    __shared__ float scol2[128];
    __shared__ float srec[4];
    __shared__ float skld[4];
    __shared__ float sfin[512];
    __shared__ bool  isLast;

    const int blk   = blockIdx.x;
    const int b     = blk >> 5;          // batch
    const int t     = threadIdx.x;
    const int lane  = t & 31;
    const int warp  = t >> 5;
    const int nl    = t & 63;            // local point A id; point B = nl + 64
    const int khalf = t >> 6;            // 0: k in [0,8), 1: k in [8,16)
    const int nA    = (blk & 31) * PTS + nl;
    const int nB    = nA + 64;

    // Stage per-(b,k) parameters (he = 0.5 * shape exponent)
    for (int i = t; i < 144; i += 128)
        sP[(i / 9) * 20 + (i % 9)] = rotate[b * 144 + i];
    if (t < 48) sP[(t / 3) * 20 + 9 + (t % 3)]  = scale [b * 48  + t];
    if (t < 32) sP[(t / 2) * 20 + 12 + (t % 2)] = 0.5f * shapes[b * 32 + t];
    if (t < 48) sM[t]                           = pam   [b * 48  + t];

    // Assign weights for both points (this thread's khalf half) -> regs + stage to sA
    float akA[8], akB[8];
    {
        const float4* avA = reinterpret_cast<const float4*>(assign)
                          + ((size_t)b * Nn + nA) * 4 + khalf * 2;
        const float4* avB = reinterpret_cast<const float4*>(assign)
                          + ((size_t)b * Nn + nB) * 4 + khalf * 2;
        const float4 a0 = avA[0], a1 = avA[1];
        const float4 b0 = avB[0], b1 = avB[1];
        akA[0]=a0.x; akA[1]=a0.y; akA[2]=a0.z; akA[3]=a0.w;
        akA[4]=a1.x; akA[5]=a1.y; akA[6]=a1.z; akA[7]=a1.w;
        akB[0]=b0.x; akB[1]=b0.y; akB[2]=b0.z; akB[3]=b0.w;
        akB[4]=b1.x; akB[5]=b1.y; akB[6]=b1.z; akB[7]=b1.w;
        float* dA = sA + nl * 17 + khalf * 8;
        float* dB = sA + (nl + 64) * 17 + khalf * 8;
        dA[0]=a0.x; dA[1]=a0.y; dA[2]=a0.z; dA[3]=a0.w;
        dA[4]=a1.x; dA[5]=a1.y; dA[6]=a1.z; dA[7]=a1.w;
        dB[0]=b0.x; dB[1]=b0.y; dB[2]=b0.z; dB[3]=b0.w;
        dB[4]=b1.x; dB[5]=b1.y; dB[6]=b1.z; dB[7]=b1.w;
    }

    // KLD slice for this block (4 elements: 4096 / 1024 blocks)
    if (t < 4) {
        const int id = blk * 4 + t;
        const float lv = logvar[id], m = mu[id];
        skld[t] = 1.f + lv - m * m - expf(lv);
    }
    __syncthreads();

    // cc = R^T mean  (48 threads, one component each)
    if (t < 48) {
        const int k = t / 3, i = t % 3;
        const float* R = sP + k * 20;
        const float* m = sM + k * 3;
        sP[k * 20 + 14 + i] = R[i] * m[0] + R[3 + i] * m[1] + R[6 + i] * m[2];
    }
    __syncthreads();

    // Point A state
    const size_t piA = ((size_t)b * Nn + nA) * 3;
    const float pxA = pc[piA], pyA = pc[piA + 1], pzA = pc[piA + 2];
    const float nxA = normals[piA], nyA = normals[piA + 1], nzA = normals[piA + 2];
    const float nnA  = nxA * nxA + nyA * nyA + nzA * nzA;
    const float inlA = rsqrtf(nnA);
    const float hxA = nxA * inlA, hyA = nyA * inlA, hzA = nzA * inlA;
    const float rnA = randn[b * Nn + nA] * 0.01f * nnA * inlA;
    // Point B state
    const size_t piB = ((size_t)b * Nn + nB) * 3;
    const float pxB = pc[piB], pyB = pc[piB + 1], pzB = pc[piB + 2];
    const float nxB = normals[piB], nyB = normals[piB + 1], nzB = normals[piB + 2];
    const float nnB  = nxB * nxB + nyB * nyB + nzB * nzB;
    const float inlB = rsqrtf(nnB);
    const float hxB = nxB * inlB, hyB = nyB * inlB, hzB = nzB * inlB;
    const float rnB = randn[b * Nn + nB] * 0.01f * nnB * inlB;

    float recA = 0.f, recB = 0.f;

    #pragma unroll
    for (int kk = 0; kk < 8; kk++) {
        const int k = khalf * 8 + kk;
        const float4* Pv = reinterpret_cast<const float4*>(sP + k * 20);
        const float4 f0 = Pv[0];   // R0 R1 R2 R3
        const float4 f1 = Pv[1];   // R4 R5 R6 R7
        const float4 f2 = Pv[2];   // R8 s0 s1 s2
        const float4 f3 = Pv[3];   // he0 he1 cc0 cc1
        const float cc2 = sP[k * 20 + 16];
        const float R0 = f0.x, R1 = f0.y, R2 = f0.z, R3 = f0.w;
        const float R4 = f1.x, R5 = f1.y, R6 = f1.z, R7 = f1.w;
        const float R8 = f2.x, s0 = f2.y, s1 = f2.z, s2 = f2.w;
        const float he0 = f3.x, he1 = f3.y, cc0 = f3.z, cc1 = f3.w;

        // ---------- point A ----------
        {
            const float c0 = fmaf(R0, pxA, fmaf(R3, pyA, fmaf(R6, pzA, -cc0)));
            const float c1 = fmaf(R1, pxA, fmaf(R4, pyA, fmaf(R7, pzA, -cc1)));
            const float c2 = fmaf(R2, pxA, fmaf(R5, pyA, fmaf(R8, pzA, -cc2)));
            const float w0 = fmaf(R0, hxA, fmaf(R3, hyA, R6 * hzA));
            const float w1 = fmaf(R1, hxA, fmaf(R4, hyA, R7 * hzA));
            const float w2 = fmaf(R2, hxA, fmaf(R5, hyA, R8 * hzA));
            const float q0 = fmaf(rnA, w0, c0);
            const float q1 = fmaf(rnA, w1, c1);
            const float q2 = fmaf(rnA, w2, c2);

            const float a0 = fabsf(w0), a1 = fabsf(w1), a2 = fabsf(w2);
            int ax = 0; float best = a0;
            if (a1 > best) { best = a1; ax = 1; }
            if (a2 > best) { best = a2; ax = 2; }
            const float wax = (ax == 0) ? w0 : ((ax == 1) ? w1 : w2);
            const float sgn = (wax > 0.f) ? 1.f : -1.f;

            float p0 = fminf(fmaxf(q0, -s0), s0);
            float p1 = fminf(fmaxf(q1, -s1), s1);
            float p2 = fminf(fmaxf(q2, -s2), s2);
            if (ax == 0)      p0 = sgn * s0;
            else if (ax == 1) p1 = sgn * s1;
            else              p2 = sgn * s2;

            const float p0sq = fmaxf(p0 * p0, 1e-38f);
            const float p1sq = fmaxf(p1 * p1, 1e-38f);
            const float p2sq = fmaxf(p2 * p2, 1e-38f);
            const float r2   = p0sq + p1sq;
            const float rho2 = r2 + p2sq;

            const float Lr = flog2(r2);
            const float Lh = flog2(rho2);
            const float L0 = flog2(p0sq);
            const float L1 = flog2(p1sq);
            const float L2 = flog2(p2sq);

            const float tphi = he0 * (Lr - Lh);
            const float u    = fmaf(-he1, Lr, tphi);
            const float X = copysignf(s0 * fexp2(fmaf(he1, L0, u)), p0);
            const float Y = copysignf(s1 * fexp2(fmaf(he1, L1, u)), p1);
            const float Z = copysignf(s2 * fexp2(he0 * (L2 - Lh)), p2);

            const float dx = X - c0, dy = Y - c1, dz = Z - c2;
            recA = fmaf(dx * dx + dy * dy + dz * dz, akA[kk], recA);
        }
        // ---------- point B ----------
        {
            const float c0 = fmaf(R0, pxB, fmaf(R3, pyB, fmaf(R6, pzB, -cc0)));
            const float c1 = fmaf(R1, pxB, fmaf(R4, pyB, fmaf(R7, pzB, -cc1)));
            const float c2 = fmaf(R2, pxB, fmaf(R5, pyB, fmaf(R8, pzB, -cc2)));
            const float w0 = fmaf(R0, hxB, fmaf(R3, hyB, R6 * hzB));
            const float w1 = fmaf(R1, hxB, fmaf(R4, hyB, R7 * hzB));
            const float w2 = fmaf(R2, hxB, fmaf(R5, hyB, R8 * hzB));
            const float q0 = fmaf(rnB, w0, c0);
            const float q1 = fmaf(rnB, w1, c1);
            const float q2 = fmaf(rnB, w2, c2);

            const float a0 = fabsf(w0), a1 = fabsf(w1), a2 = fabsf(w2);
            int ax = 0; float best = a0;
            if (a1 > best) { best = a1; ax = 1; }
            if (a2 > best) { best = a2; ax = 2; }
            const float wax = (ax == 0) ? w0 : ((ax == 1) ? w1 : w2);
            const float sgn = (wax > 0.f) ? 1.f : -1.f;

            float p0 = fminf(fmaxf(q0, -s0), s0);
            float p1 = fminf(fmaxf(q1, -s1), s1);
            float p2 = fminf(fmaxf(q2, -s2), s2);
            if (ax == 0)      p0 = sgn * s0;
            else if (ax == 1) p1 = sgn * s1;
            else              p2 = sgn * s2;

            const float p0sq = fmaxf(p0 * p0, 1e-38f);
            const float p1sq = fmaxf(p1 * p1, 1e-38f);
            const float p2sq = fmaxf(p2 * p2, 1e-38f);
            const float r2   = p0sq + p1sq;
            const float rho2 = r2 + p2sq;

            const float Lr = flog2(r2);
            const float Lh = flog2(rho2);
            const float L0 = flog2(p0sq);
            const float L1 = flog2(p1sq);
            const float L2 = flog2(p2sq);

            const float tphi = he0 * (Lr - Lh);
            const float u    = fmaf(-he1, Lr, tphi);
            const float X = copysignf(s0 * fexp2(fmaf(he1, L0, u)), p0);
            const float Y = copysignf(s1 * fexp2(fmaf(he1, L1, u)), p1);
            const float Z = copysignf(s2 * fexp2(he0 * (L2 - Lh)), p2);

            const float dx = X - c0, dy = Y - c1, dz = Z - c2;
            recB = fmaf(dx * dx + dy * dy + dz * dz, akB[kk], recB);
        }
    }

    float rec = recA + recB;

    // --- block reductions (deterministic, 4 warps) ---
    #pragma unroll
    for (int off = 16; off; off >>= 1)
        rec += __shfl_down_sync(0xffffffffu, rec, off);
    if (lane == 0) srec[warp] = rec;

    // assign column sums from sA: 8 chunks x 16 rows = 128 rows
    {
        const int kcol = t & 15, chunk = t >> 4;
        float csum = 0.f;
        #pragma unroll
        for (int i = 0; i < 16; i++)
            csum += sA[(chunk * 16 + i) * 17 + kcol];
        scol2[t] = csum;
    }
    __syncthreads();

    if (t == 0) {
        float s = srec[0] + srec[1] + srec[2] + srec[3];
        float kp = skld[0] + skld[1] + skld[2] + skld[3];
        g_comb[blk] = s * (1.0f / (32.f * 4096.f)) + kp * (-0.5f * 0.001f / 32.f);
    }
    if (t < Kn) {
        float s = 0.f;
        #pragma unroll
        for (int c = 0; c < 8; c++) s += scol2[t + c * 16];
        g_col_partial[blk * Kn + t] = s;
    }

    // --- last-block-done: fused final reduction (128 threads) ---
    __threadfence();
    __syncthreads();
    if (t == 0) {
        unsigned int v = atomicAdd(&g_count, 1u);
        isLast = (v == GRIDA - 1);
    }
    __syncthreads();
    if (!isLast) return;
    __threadfence();

    float acc = 0.f;
    #pragma unroll
    for (int i = 0; i < 8; i++) acc += g_comb[t + 128 * i];

    // cs for 512 (b,k) pairs: 4 per thread (p = t, t+128, t+256, t+384)
    #pragma unroll
    for (int pi2 = 0; pi2 < 4; pi2++) {
        const int p  = t + 128 * pi2;
        const int bb = p >> 4, kc = p & 15;
        float cs = 0.f;
        #pragma unroll
        for (int nb2 = 0; nb2 < 32; nb2++)
            cs += g_col_partial[((bb * 32 + nb2) << 4) + kc];
        sfin[p] = sqrtf(cs * (1.f / 4096.f) + 0.01f);
        // EXT: BCE-with-logits (weight 0.01)
        const float l  = exist[p];
        const float gt = (cs > 24.f) ? 1.f : 0.f;
        acc += (fmaxf(l, 0.f) - l * gt + log1pf(expf(-fabsf(l)))) * (0.01f / 512.f);
        // CST (weight 0.1)
        const float dx = pam[p * 3]     - trans[p * 3];
        const float dy = pam[p * 3 + 1] - trans[p * 3 + 1];
        const float dz = pam[p * 3 + 2] - trans[p * 3 + 2];
        acc += sqrtf(dx * dx + dy * dy + dz * dz) * (0.1f / 512.f);
    }

    // SPS: per-b mean over k of sfin, squared (weight 0.1)
    __syncthreads();
    if (t < 32) {
        float m = 0.f;
        #pragma unroll
        for (int kk2 = 0; kk2 < 16; kk2++) m += sfin[t * 16 + kk2];
        m *= (1.f / 16.f);
        acc += m * m * (0.1f / 32.f);
    }

    // block reduction of acc (4 warps)
    #pragma unroll
    for (int off = 16; off; off >>= 1)
        acc += __shfl_down_sync(0xffffffffu, acc, off);
    __syncthreads();
    if (lane == 0) srec[warp] = acc;
    __syncthreads();
    if (t == 0) {
        out[0] = srec[0] + srec[1] + srec[2] + srec[3];
        g_count = 0;   // reset for next graph replay
    }
}

extern "C" void kernel_launch(void* const* d_in, const int* in_sizes, int n_in,
                              void* d_out, int out_size)
{
    const float* pc      = (const float*)d_in[0];
    const float* normals = (const float*)d_in[1];
    const float* randn   = (const float*)d_in[2];
    const float* scale   = (const float*)d_in[3];
    const float* shapes  = (const float*)d_in[4];
    const float* rotate  = (const float*)d_in[5];
    const float* pam     = (const float*)d_in[6];
    const float* assign  = (const float*)d_in[7];
    const float* exist   = (const float*)d_in[8];
    const float* mu      = (const float*)d_in[9];
    const float* logvar  = (const float*)d_in[10];
    const float* trans   = (const float*)d_in[11];
    float* out = (float*)d_out;

    loss_fused_kernel<<<GRIDA, 128>>>(pc, normals, randn, scale, shapes, rotate,
                                      pam, assign, exist, mu, logvar, trans, out);
}

// round 12
// speedup vs baseline: 1.2216x; 1.2216x over previous
#include <cuda_runtime.h>

#define Bn 32
#define Nn 4096
#define Kn 16
#define PTS 256                 // points per block (2 per thread)
#define NBLK (Nn / PTS)         // 16 blocks per batch
#define GRIDA (Bn * NBLK)       // 512 blocks

// Deterministic scratch (no allocations allowed)
__device__ float g_comb[GRIDA];             // rec + kld partial (pre-weighted)
__device__ float g_col_partial[GRIDA * Kn]; // assign column partials
__device__ unsigned int g_count = 0;

__device__ __forceinline__ float flog2(float x) {
    float y; asm("lg2.approx.f32 %0, %1;" : "=f"(y) : "f"(x)); return y;
}
__device__ __forceinline__ float fexp2(float x) {
    float y; asm("ex2.approx.f32 %0, %1;" : "=f"(y) : "f"(x)); return y;
}

__global__ __launch_bounds__(256, 4) void loss_fused_kernel(
    const float* __restrict__ pc, const float* __restrict__ normals,
    const float* __restrict__ randn, const float* __restrict__ scale,
    const float* __restrict__ shapes, const float* __restrict__ rotate,
    const float* __restrict__ pam, const float* __restrict__ assign,
    const float* __restrict__ exist, const float* __restrict__ mu,
    const float* __restrict__ logvar, const float* __restrict__ trans,
    float* __restrict__ out)
{
    // sP stride 20: [0-8]=R, [9-11]=scale, [12]=he0,[13]=he1,[14]=he01,[15-17]=ncc=-R^T mean
    __shared__ __align__(16) float sP[Kn * 20];
    __shared__ float sM[Kn * 3];          // raw means (staging only)
    __shared__ float sA[PTS * 17];        // assign rows, stride-17 (column sums)
    __shared__ float scol2[256];
    __shared__ float srec[8];
    __shared__ float skld[8];
    __shared__ float sfin[512];
    __shared__ bool  isLast;

    const int blk   = blockIdx.x;
    const int b     = blk >> 4;          // batch
    const int t     = threadIdx.x;
    const int lane  = t & 31;
    const int warp  = t >> 5;
    const int nl    = t & 127;           // local point A id; point B = nl + 128
    const int khalf = t >> 7;            // 0: k in [0,8), 1: k in [8,16)
    const int nA    = (blk & 15) * PTS + nl;
    const int nB    = nA + 128;

    // Stage per-(b,k) parameters
    if (t < 144) sP[(t / 9) * 20 + (t % 9)]      = rotate[b * 144 + t];
    if (t < 48)  sP[(t / 3) * 20 + 9 + (t % 3)]  = scale [b * 48  + t];
    if (t < 32)  sP[(t / 2) * 20 + 12 + (t % 2)] = 0.5f * shapes[b * 32 + t];
    if (t < 48)  sM[t]                           = pam   [b * 48  + t];

    // Assign weights for both points -> regs + stage to sA (for column sums)
    float akA[8], akB[8];
    {
        const float4* avA = reinterpret_cast<const float4*>(assign)
                          + ((size_t)b * Nn + nA) * 4 + khalf * 2;
        const float4* avB = reinterpret_cast<const float4*>(assign)
                          + ((size_t)b * Nn + nB) * 4 + khalf * 2;
        const float4 a0 = avA[0], a1 = avA[1];
        const float4 b0 = avB[0], b1 = avB[1];
        akA[0]=a0.x; akA[1]=a0.y; akA[2]=a0.z; akA[3]=a0.w;
        akA[4]=a1.x; akA[5]=a1.y; akA[6]=a1.z; akA[7]=a1.w;
        akB[0]=b0.x; akB[1]=b0.y; akB[2]=b0.z; akB[3]=b0.w;
        akB[4]=b1.x; akB[5]=b1.y; akB[6]=b1.z; akB[7]=b1.w;
        float* dA = sA + nl * 17 + khalf * 8;
        float* dB = sA + (nl + 128) * 17 + khalf * 8;
        dA[0]=a0.x; dA[1]=a0.y; dA[2]=a0.z; dA[3]=a0.w;
        dA[4]=a1.x; dA[5]=a1.y; dA[6]=a1.z; dA[7]=a1.w;
        dB[0]=b0.x; dB[1]=b0.y; dB[2]=b0.z; dB[3]=b0.w;
        dB[4]=b1.x; dB[5]=b1.y; dB[6]=b1.z; dB[7]=b1.w;
    }

    // KLD slice for this block (8 elements)
    if (t < 8) {
        const int id = blk * 8 + t;
        const float lv = logvar[id], m = mu[id];
        skld[t] = 1.f + lv - m * m - expf(lv);
    }
    __syncthreads();

    // ncc = -(R^T mean); he01 = he0 - he1
    if (t < 48) {
        const int k = t / 3, i = t % 3;
        const float* R = sP + k * 20;
        const float* m = sM + k * 3;
        sP[k * 20 + 15 + i] = -(R[i] * m[0] + R[3 + i] * m[1] + R[6 + i] * m[2]);
    }
    else if (t >= 64 && t < 80) {
        const int k = t - 64;
        sP[k * 20 + 14] = sP[k * 20 + 12] - sP[k * 20 + 13];
    }
    __syncthreads();

    // Point A state
    const size_t piA = ((size_t)b * Nn + nA) * 3;
    const float pxA = pc[piA], pyA = pc[piA + 1], pzA = pc[piA + 2];
    const float nxA = normals[piA], nyA = normals[piA + 1], nzA = normals[piA + 2];
    const float nnA  = nxA * nxA + nyA * nyA + nzA * nzA;
    const float inlA = rsqrtf(nnA);
    const float hxA = nxA * inlA, hyA = nyA * inlA, hzA = nzA * inlA;
    const float rnA = randn[b * Nn + nA] * 0.01f * nnA * inlA;
    // Point B state
    const size_t piB = ((size_t)b * Nn + nB) * 3;
    const float pxB = pc[piB], pyB = pc[piB + 1], pzB = pc[piB + 2];
    const float nxB = normals[piB], nyB = normals[piB + 1], nzB = normals[piB + 2];
    const float nnB  = nxB * nxB + nyB * nyB + nzB * nzB;
    const float inlB = rsqrtf(nnB);
    const float hxB = nxB * inlB, hyB = nyB * inlB, hzB = nzB * inlB;
    const float rnB = randn[b * Nn + nB] * 0.01f * nnB * inlB;

    float recA = 0.f, recB = 0.f;

    #pragma unroll
    for (int kk = 0; kk < 8; kk++) {
        const int k = khalf * 8 + kk;
        const float4* Pv = reinterpret_cast<const float4*>(sP + k * 20);
        const float4 f0v = Pv[0];   // R0 R1 R2 R3
        const float4 f1v = Pv[1];   // R4 R5 R6 R7
        const float4 f2v = Pv[2];   // R8 s0 s1 s2
        const float4 f3v = Pv[3];   // he0 he1 he01 ncc0
        const float ncc1 = sP[k * 20 + 16];
        const float ncc2 = sP[k * 20 + 17];
        const float R0 = f0v.x, R1 = f0v.y, R2 = f0v.z, R3 = f0v.w;
        const float R4 = f1v.x, R5 = f1v.y, R6 = f1v.z, R7 = f1v.w;
        const float R8 = f2v.x, s0 = f2v.y, s1 = f2v.z, s2 = f2v.w;
        const float he0 = f3v.x, he1 = f3v.y, he01 = f3v.z, ncc0 = f3v.w;

        // ---------- point A ----------
        {
            const float c0 = fmaf(R0, pxA, fmaf(R3, pyA, fmaf(R6, pzA, ncc0)));
            const float c1 = fmaf(R1, pxA, fmaf(R4, pyA, fmaf(R7, pzA, ncc1)));
            const float c2 = fmaf(R2, pxA, fmaf(R5, pyA, fmaf(R8, pzA, ncc2)));
            const float w0 = fmaf(R0, hxA, fmaf(R3, hyA, R6 * hzA));
            const float w1 = fmaf(R1, hxA, fmaf(R4, hyA, R7 * hzA));
            const float w2 = fmaf(R2, hxA, fmaf(R5, hyA, R8 * hzA));
            const float q0 = fmaf(rnA, w0, c0);
            const float q1 = fmaf(rnA, w1, c1);
            const float q2 = fmaf(rnA, w2, c2);

            // branchless argmax+override (ties -> lowest axis, matches jnp face order)
            const float a0 = fabsf(w0), a1 = fabsf(w1), a2 = fabsf(w2);
            const bool g0 = (a0 >= a1) & (a0 >= a2);
            const bool g1 = (!g0) & (a1 >= a2);
            const bool g2 = !(g0 | g1);
            const float p0 = g0 ? copysignf(s0, w0) : fminf(fmaxf(q0, -s0), s0);
            const float p1 = g1 ? copysignf(s1, w1) : fminf(fmaxf(q1, -s1), s1);
            const float p2 = g2 ? copysignf(s2, w2) : fminf(fmaxf(q2, -s2), s2);

            const float p0sq = fmaf(p0, p0, 1e-30f);
            const float p1sq = fmaf(p1, p1, 1e-30f);
            const float p2sq = fmaf(p2, p2, 1e-30f);
            const float r2   = p0sq + p1sq;
            const float rho2 = r2 + p2sq;

            const float Lr = flog2(r2);
            const float Lh = flog2(rho2);
            const float L0 = flog2(p0sq);
            const float L1 = flog2(p1sq);
            const float L2 = flog2(p2sq);

            const float hLh = he0 * Lh;
            const float u   = fmaf(he01, Lr, -hLh);
            const float X = copysignf(s0 * fexp2(fmaf(he1, L0, u)), p0);
            const float Y = copysignf(s1 * fexp2(fmaf(he1, L1, u)), p1);
            const float Z = copysignf(s2 * fexp2(fmaf(he0, L2, -hLh)), p2);

            const float dx = X - c0, dy = Y - c1, dz = Z - c2;
            recA = fmaf(fmaf(dx, dx, fmaf(dy, dy, dz * dz)), akA[kk], recA);
        }
        // ---------- point B ----------
        {
            const float c0 = fmaf(R0, pxB, fmaf(R3, pyB, fmaf(R6, pzB, ncc0)));
            const float c1 = fmaf(R1, pxB, fmaf(R4, pyB, fmaf(R7, pzB, ncc1)));
            const float c2 = fmaf(R2, pxB, fmaf(R5, pyB, fmaf(R8, pzB, ncc2)));
            const float w0 = fmaf(R0, hxB, fmaf(R3, hyB, R6 * hzB));
            const float w1 = fmaf(R1, hxB, fmaf(R4, hyB, R7 * hzB));
            const float w2 = fmaf(R2, hxB, fmaf(R5, hyB, R8 * hzB));
            const float q0 = fmaf(rnB, w0, c0);
            const float q1 = fmaf(rnB, w1, c1);
            const float q2 = fmaf(rnB, w2, c2);

            const float a0 = fabsf(w0), a1 = fabsf(w1), a2 = fabsf(w2);
            const bool g0 = (a0 >= a1) & (a0 >= a2);
            const bool g1 = (!g0) & (a1 >= a2);
            const bool g2 = !(g0 | g1);
            const float p0 = g0 ? copysignf(s0, w0) : fminf(fmaxf(q0, -s0), s0);
            const float p1 = g1 ? copysignf(s1, w1) : fminf(fmaxf(q1, -s1), s1);
            const float p2 = g2 ? copysignf(s2, w2) : fminf(fmaxf(q2, -s2), s2);

            const float p0sq = fmaf(p0, p0, 1e-30f);
            const float p1sq = fmaf(p1, p1, 1e-30f);
            const float p2sq = fmaf(p2, p2, 1e-30f);
            const float r2   = p0sq + p1sq;
            const float rho2 = r2 + p2sq;

            const float Lr = flog2(r2);
            const float Lh = flog2(rho2);
            const float L0 = flog2(p0sq);
            const float L1 = flog2(p1sq);
            const float L2 = flog2(p2sq);

            const float hLh = he0 * Lh;
            const float u   = fmaf(he01, Lr, -hLh);
            const float X = copysignf(s0 * fexp2(fmaf(he1, L0, u)), p0);
            const float Y = copysignf(s1 * fexp2(fmaf(he1, L1, u)), p1);
            const float Z = copysignf(s2 * fexp2(fmaf(he0, L2, -hLh)), p2);

            const float dx = X - c0, dy = Y - c1, dz = Z - c2;
            recB = fmaf(fmaf(dx, dx, fmaf(dy, dy, dz * dz)), akB[kk], recB);
        }
    }

    float rec = recA + recB;

    // --- block reductions (deterministic) ---
    #pragma unroll
    for (int off = 16; off; off >>= 1)
        rec += __shfl_down_sync(0xffffffffu, rec, off);
    if (lane == 0) srec[warp] = rec;

    // assign column sums from sA: 16 chunks x 16 rows = 256 rows
    {
        const int kcol = t & 15, chunk = t >> 4;
        float csum = 0.f;
        #pragma unroll
        for (int i = 0; i < 16; i++)
            csum += sA[(chunk * 16 + i) * 17 + kcol];
        scol2[t] = csum;
    }
    __syncthreads();

    if (t == 0) {
        float s = 0.f;
        #pragma unroll
        for (int w = 0; w < 8; w++) s += srec[w];
        float kp = 0.f;
        #pragma unroll
        for (int i = 0; i < 8; i++) kp += skld[i];
        g_comb[blk] = s * (1.0f / (32.f * 4096.f)) + kp * (-0.5f * 0.001f / 32.f);
    }
    if (t < Kn) {
        float s = 0.f;
        #pragma unroll
        for (int c = 0; c < 16; c++) s += scol2[t + c * 16];
        g_col_partial[blk * Kn + t] = s;
    }

    // --- last-block-done: fused final reduction ---
    __threadfence();
    __syncthreads();
    if (t == 0) {
        unsigned int v = atomicAdd(&g_count, 1u);
        isLast = (v == GRIDA - 1);
    }
    __syncthreads();
    if (!isLast) return;
    __threadfence();

    float acc = g_comb[t] + g_comb[t + 256];

    // cs for (b,k) pairs p = t and p = t+256
    float cs0 = 0.f, cs1 = 0.f;
    {
        const int b0 = t >> 4, b1 = (t + 256) >> 4, kc = t & 15;
        #pragma unroll
        for (int nb2 = 0; nb2 < 16; nb2++) {
            cs0 += g_col_partial[((b0 * 16 + nb2) << 4) + kc];
            cs1 += g_col_partial[((b1 * 16 + nb2) << 4) + kc];
        }
        sfin[t]       = sqrtf(cs0 * (1.f / 4096.f) + 0.01f);
        sfin[t + 256] = sqrtf(cs1 * (1.f / 4096.f) + 0.01f);
    }

    // EXT: BCE-with-logits for pairs t, t+256 (weight 0.01)
    {
        const float l0 = exist[t], l1 = exist[t + 256];
        const float g0 = (cs0 > 24.f) ? 1.f : 0.f;
        const float g1 = (cs1 > 24.f) ? 1.f : 0.f;
        const float e0v = fmaxf(l0, 0.f) - l0 * g0 + log1pf(expf(-fabsf(l0)));
        const float e1v = fmaxf(l1, 0.f) - l1 * g1 + log1pf(expf(-fabsf(l1)));
        acc += (e0v + e1v) * (0.01f / 512.f);
    }

    // CST: 512 (b,k) pairs, 2 per thread (weight 0.1)
    {
        const int p0i = t * 3, p1i = (t + 256) * 3;
        float dx0 = pam[p0i]     - trans[p0i];
        float dy0 = pam[p0i + 1] - trans[p0i + 1];
        float dz0 = pam[p0i + 2] - trans[p0i + 2];
        float dx1 = pam[p1i]     - trans[p1i];
        float dy1 = pam[p1i + 1] - trans[p1i + 1];
        float dz1 = pam[p1i + 2] - trans[p1i + 2];
        acc += (sqrtf(dx0 * dx0 + dy0 * dy0 + dz0 * dz0) +
                sqrtf(dx1 * dx1 + dy1 * dy1 + dz1 * dz1)) * (0.1f / 512.f);
    }

    // SPS: per-b mean over k of sfin, squared (weight 0.1)
    __syncthreads();
    if (t < 32) {
        float m = 0.f;
        #pragma unroll
        for (int kk2 = 0; kk2 < 16; kk2++) m += sfin[t * 16 + kk2];
        m *= (1.f / 16.f);
        acc += m * m * (0.1f / 32.f);
    }

    // block reduction of acc
    #pragma unroll
    for (int off = 16; off; off >>= 1)
        acc += __shfl_down_sync(0xffffffffu, acc, off);
    __syncthreads();
    if (lane == 0) srec[warp] = acc;
    __syncthreads();
    if (t == 0) {
        float s = 0.f;
        #pragma unroll
        for (int w = 0; w < 8; w++) s += srec[w];
        out[0] = s;
        g_count = 0;   // reset for next graph replay
    }
}

extern "C" void kernel_launch(void* const* d_in, const int* in_sizes, int n_in,
                              void* d_out, int out_size)
{
    const float* pc      = (const float*)d_in[0];
    const float* normals = (const float*)d_in[1];
    const float* randn   = (const float*)d_in[2];
    const float* scale   = (const float*)d_in[3];
    const float* shapes  = (const float*)d_in[4];
    const float* rotate  = (const float*)d_in[5];
    const float* pam     = (const float*)d_in[6];
    const float* assign  = (const float*)d_in[7];
    const float* exist   = (const float*)d_in[8];
    const float* mu      = (const float*)d_in[9];
    const float* logvar  = (const float*)d_in[10];
    const float* trans   = (const float*)d_in[11];
    float* out = (float*)d_out;

    loss_fused_kernel<<<GRIDA, 256>>>(pc, normals, randn, scale, shapes, rotate,
                                      pam, assign, exist, mu, logvar, trans, out);
}